// round 2
// baseline (speedup 1.0000x reference)
#include <cuda_runtime.h>
#include <cstdint>
#include <cstddef>

#define B_    16
#define N_    2048
#define FIN   256
#define FOUT  128
#define MTOT  (B_ * N_)

// Scratch (device globals — no allocation allowed)
__device__ float g_h[(size_t)MTOT * FOUT];   // 16 MB
__device__ float g_f1[MTOT];
__device__ float g_f2[MTOT];

// packed dual-FMA: d = a*b + d on fp32 pairs (Blackwell f32x2 pipe)
__device__ __forceinline__ void ffma2(unsigned long long& d,
                                      unsigned long long a,
                                      unsigned long long b) {
    asm("fma.rn.f32x2 %0, %1, %2, %0;" : "+l"(d) : "l"(a), "l"(b));
}

// ---------------------------------------------------------------------------
// Kernel A: h[m, :] = input[m, :] @ W   (M=32768, K=256, N=128)
// Tile 64 rows x 128 cols, K-chunks of 32. 256 threads, 8x4 per-thread tile.
// ---------------------------------------------------------------------------
__global__ __launch_bounds__(256) void k_gemm_h(const float* __restrict__ inp,
                                                const float* __restrict__ W) {
    __shared__ float inp_s[64][32];
    __shared__ float W_s[32][128];

    const int tid  = threadIdx.x;
    const int m0   = blockIdx.x * 64;
    const int fcol = (tid & 31) * 4;
    const int irow = (tid >> 5) * 8;

    float acc[8][4];
#pragma unroll
    for (int r = 0; r < 8; r++)
#pragma unroll
        for (int c = 0; c < 4; c++) acc[r][c] = 0.f;

    for (int kk = 0; kk < FIN; kk += 32) {
        // load input tile: 64x32 = 512 float4
#pragma unroll
        for (int t = 0; t < 2; t++) {
            int idx = tid + t * 256;
            int r = idx >> 3, c = idx & 7;
            *(float4*)&inp_s[r][c * 4] =
                *(const float4*)&inp[(size_t)(m0 + r) * FIN + kk + c * 4];
        }
        // load W tile: 32x128 = 1024 float4
#pragma unroll
        for (int t = 0; t < 4; t++) {
            int idx = tid + t * 256;
            int k = idx >> 5, c = idx & 31;
            *(float4*)&W_s[k][c * 4] =
                *(const float4*)&W[(size_t)(kk + k) * FOUT + c * 4];
        }
        __syncthreads();

#pragma unroll
        for (int k = 0; k < 32; k++) {
            float4 bv = *(float4*)&W_s[k][fcol];
#pragma unroll
            for (int r = 0; r < 8; r++) {
                float a = inp_s[irow + r][k];
                acc[r][0] = fmaf(a, bv.x, acc[r][0]);
                acc[r][1] = fmaf(a, bv.y, acc[r][1]);
                acc[r][2] = fmaf(a, bv.z, acc[r][2]);
                acc[r][3] = fmaf(a, bv.w, acc[r][3]);
            }
        }
        __syncthreads();
    }

#pragma unroll
    for (int r = 0; r < 8; r++) {
        float4 o = make_float4(acc[r][0], acc[r][1], acc[r][2], acc[r][3]);
        *(float4*)&g_h[(size_t)(m0 + irow + r) * FOUT + fcol] = o;
    }
}

// ---------------------------------------------------------------------------
// Kernel B: f1[m] = h[m,:] . a1 ; f2[m] = h[m,:] . a2  (one warp per row)
// ---------------------------------------------------------------------------
__global__ __launch_bounds__(256) void k_f12(const float* __restrict__ a1,
                                             const float* __restrict__ a2) {
    const int row  = blockIdx.x * 8 + (threadIdx.x >> 5);
    const int lane = threadIdx.x & 31;
    const float* hr = g_h + (size_t)row * FOUT;
    float s1 = 0.f, s2 = 0.f;
#pragma unroll
    for (int c = lane; c < FOUT; c += 32) {
        float hv = hr[c];
        s1 = fmaf(hv, __ldg(a1 + c), s1);
        s2 = fmaf(hv, __ldg(a2 + c), s2);
    }
#pragma unroll
    for (int o = 16; o; o >>= 1) {
        s1 += __shfl_xor_sync(0xffffffffu, s1, o);
        s2 += __shfl_xor_sync(0xffffffffu, s2, o);
    }
    if (lane == 0) { g_f1[row] = s1; g_f2[row] = s2; }
}

// ---------------------------------------------------------------------------
// Kernel C: fused masked-softmax attention + output elu.
// CTA: (64 rows i) x (128 feats), loop j in chunks of 64.
// Single-pass softmax (no max subtraction needed: |e| <= ~30, exp fits fp32).
// Weights stored duplicated (w,w) so inner GEMM is pure LDS.64 + FFMA2.
// ---------------------------------------------------------------------------
#define SMEM_C ((2 * 64 * 128 + 64) * (int)sizeof(float))  // 65,792 B

__global__ __launch_bounds__(256) void k_attn(const int* __restrict__ adj,
                                              float* __restrict__ out) {
    extern __shared__ float smem[];
    float (*h_s)[128]  = (float(*)[128])smem;                  // 64 x 128
    float (*w2_s)[128] = (float(*)[128])(smem + 64 * 128);     // 64 rows x 64 (w,w) pairs
    float* s_s = smem + 2 * 64 * 128;                          // 64 row-denominators

    const int tid  = threadIdx.x;
    const int b    = blockIdx.y;
    const int i0   = blockIdx.x * 64;
    const int fcol = (tid & 31) * 4;
    const int irow = (tid >> 5) * 8;

    const float* f1p = g_f1 + b * N_ + i0;
    const float* f2p = g_f2 + b * N_;
    const float* hb  = g_h + (size_t)b * N_ * FOUT;
    const int* adjb  = adj + ((size_t)b * N_ + i0) * N_;

    if (tid < 64) s_s[tid] = 0.f;

    unsigned long long acc2[8][2];
#pragma unroll
    for (int r = 0; r < 8; r++) { acc2[r][0] = 0ull; acc2[r][1] = 0ull; }

    __syncthreads();

    for (int j0 = 0; j0 < N_; j0 += 64) {
        // ---- load h chunk: 64x128 floats ----
#pragma unroll
        for (int t = 0; t < 8; t++) {
            int idx = tid + t * 256;
            int jr = idx >> 5, jc = idx & 31;
            *(float4*)&h_s[jr][jc * 4] =
                *(const float4*)&hb[(size_t)(j0 + jr) * FOUT + jc * 4];
        }
        // ---- compute masked exp weights (duplicated pairs) ----
#pragma unroll
        for (int t = 0; t < 4; t++) {
            int idx = tid + t * 256;
            int wi  = idx >> 4;
            int wj4 = (idx & 15) * 4;
            int4 av = *(const int4*)&adjb[(size_t)wi * N_ + j0 + wj4];
            float fi = __ldg(f1p + wi);
            int am[4] = {av.x, av.y, av.z, av.w};
#pragma unroll
            for (int k = 0; k < 4; k++) {
                float e = fi + __ldg(f2p + j0 + wj4 + k);
                e = e > 0.f ? e : 0.2f * e;           // leaky relu
                float w = (am[k] > 0) ? __expf(e) : 0.f;
                *(float2*)&w2_s[wi][2 * (wj4 + k)] = make_float2(w, w);
            }
        }
        __syncthreads();

        // ---- accumulate softmax denominators (deterministic order) ----
        if (tid < 64) {
            float ss = 0.f;
#pragma unroll
            for (int j = 0; j < 64; j++) ss += w2_s[tid][2 * j];
            s_s[tid] += ss;
        }

        // ---- weighted accumulation: acc[i,f] += w[i,j] * h[j,f] (FFMA2) ----
#pragma unroll 16
        for (int j = 0; j < 64; j++) {
            unsigned long long h01 = *(const unsigned long long*)&h_s[j][fcol];
            unsigned long long h23 = *(const unsigned long long*)&h_s[j][fcol + 2];
#pragma unroll
            for (int r = 0; r < 8; r++) {
                unsigned long long wv =
                    *(const unsigned long long*)&w2_s[irow + r][2 * j];
                ffma2(acc2[r][0], wv, h01);
                ffma2(acc2[r][1], wv, h23);
            }
        }
        __syncthreads();
    }

    // ---- epilogue: divide by denominator, elu, store ----
#pragma unroll
    for (int r = 0; r < 8; r++) {
        float s   = s_s[irow + r];
        float inv = (s > 0.f) ? (1.f / s) : 0.f;
        union { unsigned long long u; float2 f; } c0, c1;
        c0.u = acc2[r][0];
        c1.u = acc2[r][1];
        float4 o;
        float v;
        v = c0.f.x * inv; o.x = v > 0.f ? v : expm1f(v);
        v = c0.f.y * inv; o.y = v > 0.f ? v : expm1f(v);
        v = c1.f.x * inv; o.z = v > 0.f ? v : expm1f(v);
        v = c1.f.y * inv; o.w = v > 0.f ? v : expm1f(v);
        *(float4*)&out[((size_t)b * N_ + i0 + irow + r) * FOUT + fcol] = o;
    }
}

// ---------------------------------------------------------------------------
extern "C" void kernel_launch(void* const* d_in, const int* in_sizes, int n_in,
                              void* d_out, int out_size) {
    const float* inp = (const float*)d_in[0];
    const int*   adj = (const int*)d_in[1];
    const float* W   = (const float*)d_in[2];
    const float* a1  = (const float*)d_in[3];
    const float* a2  = (const float*)d_in[4];
    float* out = (float*)d_out;

    cudaFuncSetAttribute(k_attn, cudaFuncAttributeMaxDynamicSharedMemorySize,
                         SMEM_C);

    k_gemm_h<<<MTOT / 64, 256>>>(inp, W);
    k_f12<<<MTOT / 8, 256>>>(a1, a2);
    dim3 gc(N_ / 64, B_);
    k_attn<<<gc, 256, SMEM_C>>>(adj, out);
}

// round 5
// speedup vs baseline: 3.3628x; 3.3628x over previous
#include <cuda_runtime.h>
#include <cuda_bf16.h>
#include <cstdint>
#include <cstddef>

#define B_    16
#define N_    2048
#define FIN   256
#define FOUT  128
#define MTOT  (B_ * N_)
#define JC    64
#define NCH   (N_ / JC)

// ---------------- device scratch (no allocation allowed) ----------------
__device__ float g_h[(size_t)MTOT * FOUT];                 // 16 MB
__device__ float g_f1[MTOT];
__device__ float g_f2[MTOT];
__device__ __nv_bfloat16 g_hT_hi[(size_t)B_ * FOUT * N_];  // 8 MB  [b][f][n]
__device__ __nv_bfloat16 g_hT_lo[(size_t)B_ * FOUT * N_];  // 8 MB

// ---------------- PTX helpers (sm_80-compatible only) ----------------
__device__ __forceinline__ uint32_t smem_u32(const void* p) {
    uint32_t a;
    asm("{ .reg .u64 t; cvta.to.shared.u64 t, %1; cvt.u32.u64 %0, t; }"
        : "=r"(a) : "l"(p));
    return a;
}
__device__ __forceinline__ void ldsm_x4(uint32_t* r, uint32_t a) {
    asm volatile("ldmatrix.sync.aligned.m8n8.x4.shared.b16 {%0,%1,%2,%3}, [%4];"
                 : "=r"(r[0]), "=r"(r[1]), "=r"(r[2]), "=r"(r[3]) : "r"(a));
}
__device__ __forceinline__ void ldsm_x2(uint32_t* r, uint32_t a) {
    asm volatile("ldmatrix.sync.aligned.m8n8.x2.shared.b16 {%0,%1}, [%2];"
                 : "=r"(r[0]), "=r"(r[1]) : "r"(a));
}
__device__ __forceinline__ void mma16816(float* d, const uint32_t* a,
                                         const uint32_t* b) {
    asm volatile(
        "mma.sync.aligned.m16n8k16.row.col.f32.bf16.bf16.f32 "
        "{%0,%1,%2,%3}, {%4,%5,%6,%7}, {%8,%9}, {%0,%1,%2,%3};"
        : "+f"(d[0]), "+f"(d[1]), "+f"(d[2]), "+f"(d[3])
        : "r"(a[0]), "r"(a[1]), "r"(a[2]), "r"(a[3]), "r"(b[0]), "r"(b[1]));
}
__device__ __forceinline__ void cpasync16(uint32_t dst, const void* src) {
    asm volatile("cp.async.cg.shared.global [%0], [%1], 16;"
                 :: "r"(dst), "l"(src) : "memory");
}

// ---------------------------------------------------------------------------
// Kernel A: h = input @ W   (known good)
// ---------------------------------------------------------------------------
__global__ __launch_bounds__(256) void k_gemm_h(const float* __restrict__ inp,
                                                const float* __restrict__ W) {
    __shared__ float inp_s[64][32];
    __shared__ float W_s[32][128];
    const int tid  = threadIdx.x;
    const int m0   = blockIdx.x * 64;
    const int fcol = (tid & 31) * 4;
    const int irow = (tid >> 5) * 8;

    float acc[8][4];
#pragma unroll
    for (int r = 0; r < 8; r++)
#pragma unroll
        for (int c = 0; c < 4; c++) acc[r][c] = 0.f;

    for (int kk = 0; kk < FIN; kk += 32) {
#pragma unroll
        for (int t = 0; t < 2; t++) {
            int idx = tid + t * 256;
            int r = idx >> 3, c = idx & 7;
            *(float4*)&inp_s[r][c * 4] =
                *(const float4*)&inp[(size_t)(m0 + r) * FIN + kk + c * 4];
        }
#pragma unroll
        for (int t = 0; t < 4; t++) {
            int idx = tid + t * 256;
            int k = idx >> 5, c = idx & 31;
            *(float4*)&W_s[k][c * 4] =
                *(const float4*)&W[(size_t)(kk + k) * FOUT + c * 4];
        }
        __syncthreads();
#pragma unroll
        for (int k = 0; k < 32; k++) {
            float4 bv = *(float4*)&W_s[k][fcol];
#pragma unroll
            for (int r = 0; r < 8; r++) {
                float a = inp_s[irow + r][k];
                acc[r][0] = fmaf(a, bv.x, acc[r][0]);
                acc[r][1] = fmaf(a, bv.y, acc[r][1]);
                acc[r][2] = fmaf(a, bv.z, acc[r][2]);
                acc[r][3] = fmaf(a, bv.w, acc[r][3]);
            }
        }
        __syncthreads();
    }
#pragma unroll
    for (int r = 0; r < 8; r++) {
        float4 o = make_float4(acc[r][0], acc[r][1], acc[r][2], acc[r][3]);
        *(float4*)&g_h[(size_t)(m0 + irow + r) * FOUT + fcol] = o;
    }
}

// ---------------------------------------------------------------------------
// Kernel B: f1/f2 projections
// ---------------------------------------------------------------------------
__global__ __launch_bounds__(256) void k_f12(const float* __restrict__ a1,
                                             const float* __restrict__ a2) {
    const int row  = blockIdx.x * 8 + (threadIdx.x >> 5);
    const int lane = threadIdx.x & 31;
    const float* hr = g_h + (size_t)row * FOUT;
    float s1 = 0.f, s2 = 0.f;
#pragma unroll
    for (int c = lane; c < FOUT; c += 32) {
        float hv = hr[c];
        s1 = fmaf(hv, __ldg(a1 + c), s1);
        s2 = fmaf(hv, __ldg(a2 + c), s2);
    }
#pragma unroll
    for (int o = 16; o; o >>= 1) {
        s1 += __shfl_xor_sync(0xffffffffu, s1, o);
        s2 += __shfl_xor_sync(0xffffffffu, s2, o);
    }
    if (lane == 0) { g_f1[row] = s1; g_f2[row] = s2; }
}

// ---------------------------------------------------------------------------
// Kernel C: transpose + bf16 hi/lo split: g_hT_*[b][f][n] from g_h[b][n][f]
// ---------------------------------------------------------------------------
__global__ __launch_bounds__(256) void k_conv() {
    __shared__ float ts[32][33];
    const int b = blockIdx.z, f0 = blockIdx.y * 32, n0 = blockIdx.x * 32;
    const int tx = threadIdx.x, ty = threadIdx.y;
#pragma unroll
    for (int r = 0; r < 4; r++) {
        int n = n0 + ty + r * 8;
        ts[ty + r * 8][tx] = g_h[((size_t)(b * N_ + n)) * FOUT + f0 + tx];
    }
    __syncthreads();
#pragma unroll
    for (int r = 0; r < 4; r++) {
        int f = f0 + ty + r * 8;
        float v = ts[tx][ty + r * 8];
        __nv_bfloat16 hi = __float2bfloat16(v);
        float lo = v - __bfloat162float(hi);
        size_t o = ((size_t)(b * FOUT + f)) * N_ + n0 + tx;
        g_hT_hi[o] = hi;
        g_hT_lo[o] = __float2bfloat16(lo);
    }
}

// ---------------------------------------------------------------------------
// Kernel D: mma.sync (HMMA bf16) fused attention.
// CTA = 128 i-rows x 128 feats; 8 warps x (64x32) tiles; j-chunks of 64.
// P = exp weights split hi/lo bf16; H pre-split/pre-transposed (g_hT).
// 3-term product: Phi*Hhi + Phi*Hlo + Plo*Hhi (fp32 accum in registers).
// Row denominators exact fp32. Smem rows padded to 144 B (conflict-free LDSM).
// ---------------------------------------------------------------------------
#define SA_DEN   0
#define SA_PHI   512
#define SA_PLO   (SA_PHI + 18432)
#define SA_HHI   (SA_PLO + 18432)
#define SA_HLO   (SA_HHI + 18432)
#define SA_TOTAL (SA_HLO + 18432)   // 74,240 B

__global__ __launch_bounds__(256, 2) void k_attn_mma(const int* __restrict__ adj,
                                                     float* __restrict__ out) {
    extern __shared__ char smem[];
    const uint32_t sb = smem_u32(smem);
    const int tid = threadIdx.x;
    const int b = blockIdx.y, i0 = blockIdx.x * 128;

    // ---- P-gen mapping: 2 threads per i-row, 32 j each ----
    const int pi = tid >> 1;
    const int pj = (tid & 1) * 32;
    const float f1v = g_f1[b * N_ + i0 + pi];
    const float* f2b = g_f2 + b * N_;
    const int* adjr = adj + (size_t)(b * N_ + i0 + pi) * N_;
    __nv_bfloat162* phir = (__nv_bfloat162*)(smem + SA_PHI + pi * 144 + pj * 2);
    __nv_bfloat162* plor = (__nv_bfloat162*)(smem + SA_PLO + pi * 144 + pj * 2);
    float den = 0.f;

    // ---- MMA mapping: warp w -> (m0, n0) tile ----
    const int w = tid >> 5, lane = tid & 31;
    const int m0 = (w >> 2) * 64, n0 = (w & 3) * 32;
    const uint32_t aHi = sb + SA_PHI + (uint32_t)(m0 + (lane & 15)) * 144 +
                         (uint32_t)(lane & 16);           // ((lane&16)>>1)*2 bytes
    const uint32_t aLo = aHi + (SA_PLO - SA_PHI);
    const uint32_t bHi = sb + SA_HHI + (uint32_t)(n0 + (lane & 7)) * 144 +
                         (uint32_t)((lane & 8) * 2);
    const uint32_t bLo = bHi + (SA_HLO - SA_HHI);

    float acc[16][4];
#pragma unroll
    for (int t = 0; t < 16; t++)
#pragma unroll
        for (int q = 0; q < 4; q++) acc[t][q] = 0.f;

    // prefetch first half of chunk-0 adjacency
    int4 apre[4];
#pragma unroll
    for (int q = 0; q < 4; q++)
        apre[q] = ((const int4*)adjr)[(pj >> 2) + q];

    for (int c = 0; c < NCH; c++) {
        const int j0 = c * JC;

        // second half adj for this chunk (issues early, consumed below)
        int4 a2[4];
#pragma unroll
        for (int q = 0; q < 4; q++)
            a2[q] = ((const int4*)adjr)[((j0 + pj) >> 2) + 4 + q];

        // ---- P-gen: 32 masked-exp weights, hi/lo split ----
#pragma unroll
        for (int q = 0; q < 8; q++) {
            int4 av = (q < 4) ? apre[q] : a2[q - 4];
            float4 f2v = *(const float4*)&f2b[j0 + pj + q * 4];
            float e0 = f1v + f2v.x, e1 = f1v + f2v.y;
            float e2 = f1v + f2v.z, e3 = f1v + f2v.w;
            e0 = fmaxf(e0, 0.2f * e0);
            e1 = fmaxf(e1, 0.2f * e1);
            e2 = fmaxf(e2, 0.2f * e2);
            e3 = fmaxf(e3, 0.2f * e3);
            float w0 = (av.x > 0) ? __expf(e0) : 0.f;
            float w1 = (av.y > 0) ? __expf(e1) : 0.f;
            float w2 = (av.z > 0) ? __expf(e2) : 0.f;
            float w3 = (av.w > 0) ? __expf(e3) : 0.f;
            den += (w0 + w1) + (w2 + w3);
            __nv_bfloat162 h01 = __floats2bfloat162_rn(w0, w1);
            __nv_bfloat162 h23 = __floats2bfloat162_rn(w2, w3);
            __nv_bfloat162 l01 = __floats2bfloat162_rn(
                w0 - __bfloat162float(h01.x), w1 - __bfloat162float(h01.y));
            __nv_bfloat162 l23 = __floats2bfloat162_rn(
                w2 - __bfloat162float(h23.x), w3 - __bfloat162float(h23.y));
            phir[q * 2] = h01;
            phir[q * 2 + 1] = h23;
            plor[q * 2] = l01;
            plor[q * 2 + 1] = l23;
        }

        // prefetch next chunk's first adj half (completes during MMA)
        if (c + 1 < NCH) {
#pragma unroll
            for (int q = 0; q < 4; q++)
                apre[q] = ((const int4*)adjr)[((j0 + JC + pj) >> 2) + q];
        }

        // ---- H hi/lo tiles via cp.async (128 f-rows x 64 j bf16 each) ----
#pragma unroll
        for (int k = 0; k < 8; k++) {
            int idx = tid + k * 256;
            int bufl = idx >> 10;
            int rem = idx & 1023;
            int f = rem >> 3, jg = rem & 7;
            uint32_t dst = sb + (bufl ? SA_HLO : SA_HHI) + f * 144 + jg * 16;
            const __nv_bfloat16* src =
                (bufl ? g_hT_lo : g_hT_hi) + ((size_t)(b * FOUT + f)) * N_ + j0 + jg * 8;
            cpasync16(dst, src);
        }
        asm volatile("cp.async.commit_group;" ::: "memory");
        asm volatile("cp.async.wait_group 0;" ::: "memory");
        __syncthreads();

        // ---- 192 HMMA per warp: 4 k-steps x 16 tiles x 3 split terms ----
#pragma unroll
        for (int k = 0; k < JC; k += 16) {
            uint32_t bh[4][2], bl[4][2];
#pragma unroll
            for (int nt = 0; nt < 4; nt++) {
                ldsm_x2(bh[nt], bHi + nt * 8 * 144 + k * 2);
                ldsm_x2(bl[nt], bLo + nt * 8 * 144 + k * 2);
            }
#pragma unroll
            for (int mt = 0; mt < 4; mt++) {
                uint32_t ah[4], al[4];
                ldsm_x4(ah, aHi + mt * 16 * 144 + k * 2);
                ldsm_x4(al, aLo + mt * 16 * 144 + k * 2);
#pragma unroll
                for (int nt = 0; nt < 4; nt++) {
                    mma16816(acc[mt * 4 + nt], ah, bh[nt]);
                    mma16816(acc[mt * 4 + nt], ah, bl[nt]);
                    mma16816(acc[mt * 4 + nt], al, bh[nt]);
                }
            }
        }
        __syncthreads();
    }

    // ---- denominator: pair-reduce (threads 2r, 2r+1 share row r) ----
    den += __shfl_xor_sync(0xffffffffu, den, 1);
    if ((tid & 1) == 0) ((float*)(smem + SA_DEN))[pi] = den;
    __syncthreads();

    // ---- epilogue: divide, elu, store (direct STG.64) ----
    const float* dsm = (const float*)(smem + SA_DEN);
#pragma unroll
    for (int mt = 0; mt < 4; mt++) {
        int r0 = m0 + mt * 16 + (lane >> 2);
        float d0 = dsm[r0], d1 = dsm[r0 + 8];
        float inv0 = (d0 > 0.f) ? (1.f / d0) : 0.f;
        float inv1 = (d1 > 0.f) ? (1.f / d1) : 0.f;
#pragma unroll
        for (int nt = 0; nt < 4; nt++) {
            int col = n0 + nt * 8 + (lane & 3) * 2;
            const float* a4 = acc[mt * 4 + nt];
            float v;
            float2 o;
            v = a4[0] * inv0; o.x = (v > 0.f) ? v : expm1f(v);
            v = a4[1] * inv0; o.y = (v > 0.f) ? v : expm1f(v);
            *(float2*)&out[((size_t)(b * N_ + i0 + r0)) * FOUT + col] = o;
            v = a4[2] * inv1; o.x = (v > 0.f) ? v : expm1f(v);
            v = a4[3] * inv1; o.y = (v > 0.f) ? v : expm1f(v);
            *(float2*)&out[((size_t)(b * N_ + i0 + r0 + 8)) * FOUT + col] = o;
        }
    }
}

// ---------------------------------------------------------------------------
extern "C" void kernel_launch(void* const* d_in, const int* in_sizes, int n_in,
                              void* d_out, int out_size) {
    const float* inp = (const float*)d_in[0];
    const int*   adj = (const int*)d_in[1];
    const float* W   = (const float*)d_in[2];
    const float* a1  = (const float*)d_in[3];
    const float* a2  = (const float*)d_in[4];
    float* out = (float*)d_out;

    cudaFuncSetAttribute(k_attn_mma, cudaFuncAttributeMaxDynamicSharedMemorySize,
                         SA_TOTAL);

    k_gemm_h<<<MTOT / 64, 256>>>(inp, W);
    dim3 gconv(N_ / 32, FOUT / 32, B_);
    k_conv<<<gconv, dim3(32, 8)>>>();
    k_f12<<<MTOT / 8, 256>>>(a1, a2);
    dim3 gattn(N_ / 128, B_);
    k_attn_mma<<<gattn, 256, SA_TOTAL>>>(adj, out);
}